// round 15
// baseline (speedup 1.0000x reference)
#include <cuda_runtime.h>
#include <cstdint>
#include <cstddef>

#define N_    16
#define C_    64
#define H_    112
#define W_DIM 112
#define O_    128
#define NUMEL_X (N_*C_*H_*W_DIM)   // 12,845,056
#define NUMEL_W (O_*C_*9)          // 73,728
#define TILE_W 32
#define NPIX   (N_*H_*W_DIM)       // 200704 pixels
#define NTILES (NPIX/128)          // 1568  (12544 = 98*128: tiles never cross n)
#define GEMM_GRID 148
#define O_IMMA 56                  // IMMA half: o[0:56), dp4a half: o[56:128)

// ---- device scratch (no allocation allowed) ----
__device__ unsigned int g_absmax[2];               // [0]=x, [1]=W (float bits, >=0)
__device__ int g_flag;                             // 1 => mma path failed, use fallback
__device__ int8_t g_qx[(size_t)NPIX*C_];           // NHWC int8
__device__ int8_t g_qw[(size_t)O_*9*C_];           // [O][tap*64+c] int8 (= B rows, K-major)

__device__ __forceinline__ uint32_t smem_u32(const void* p) {
    uint32_t a;
    asm("{ .reg .u64 t; cvta.to.shared.u64 t, %1; cvt.u32.u64 %0, t; }" : "=r"(a) : "l"(p));
    return a;
}

// ---- warp-level int8 tensor core ops (base-target PTX, no tcgen05) ----
__device__ __forceinline__ void ldsm_x4(uint32_t& r0, uint32_t& r1, uint32_t& r2, uint32_t& r3,
                                        uint32_t addr) {
    asm volatile("ldmatrix.sync.aligned.m8n8.x4.shared.b16 {%0,%1,%2,%3}, [%4];"
                 : "=r"(r0), "=r"(r1), "=r"(r2), "=r"(r3) : "r"(addr));
}

__device__ __forceinline__ void mma_s8(int* c, uint32_t a0, uint32_t a1, uint32_t a2, uint32_t a3,
                                       uint32_t b0, uint32_t b1) {
    asm volatile("mma.sync.aligned.m16n8k32.row.col.s32.s8.s8.s32 "
                 "{%0,%1,%2,%3}, {%4,%5,%6,%7}, {%8,%9}, {%0,%1,%2,%3};"
                 : "+r"(c[0]), "+r"(c[1]), "+r"(c[2]), "+r"(c[3])
                 : "r"(a0), "r"(a1), "r"(a2), "r"(a3), "r"(b0), "r"(b1));
}

// ---- common small kernels ----
__global__ void init_kernel() {
    g_absmax[0] = 0u;
    g_absmax[1] = 0u;
    g_flag = 0;
}

__device__ __forceinline__ void block_max_atomic(float v, unsigned int* target) {
    #pragma unroll
    for (int off = 16; off; off >>= 1)
        v = fmaxf(v, __shfl_xor_sync(0xffffffffu, v, off));
    __shared__ float s[32];
    int lane = threadIdx.x & 31, wid = threadIdx.x >> 5;
    if (lane == 0) s[wid] = v;
    __syncthreads();
    if (wid == 0) {
        int nw = (blockDim.x + 31) >> 5;
        v = (lane < nw) ? s[lane] : 0.f;
        #pragma unroll
        for (int off = 16; off; off >>= 1)
            v = fmaxf(v, __shfl_xor_sync(0xffffffffu, v, off));
        if (lane == 0) atomicMax(target, __float_as_uint(v));
    }
}

__global__ void absmax_kernel(const float4* __restrict__ p, int n4, int which) {
    float m = 0.f;
    for (int i = blockIdx.x * blockDim.x + threadIdx.x; i < n4; i += gridDim.x * blockDim.x) {
        float4 v = p[i];
        m = fmaxf(m, fmaxf(fmaxf(fabsf(v.x), fabsf(v.y)), fmaxf(fabsf(v.z), fabsf(v.w))));
    }
    block_max_atomic(m, &g_absmax[which]);
}

__device__ __forceinline__ float load_scale(int which) {
    return fmaxf(__uint_as_float(g_absmax[which]) / 127.0f, 1e-8f);
}

__device__ __forceinline__ uint32_t q8(float v, float inv) {
    float q = fminf(fmaxf(rintf(v * inv), -127.f), 127.f);
    return (uint32_t)(uint8_t)(int8_t)(int)q;
}

// Quantize x NCHW -> NHWC int8. One block per 2 (n,h) rows.
__global__ void __launch_bounds__(256) quant_x_kernel(const float* __restrict__ x) {
    __shared__ uint32_t sq[2 * W_DIM * 17];
    int nh0 = blockIdx.x * 2;
    float inv = 1.0f / load_scale(0);
    for (int idx = threadIdx.x; idx < 896; idx += 256) {
        int rr = idx / 448;
        int rem = idx % 448;
        int c4 = rem / 28, w4 = rem % 28;
        int nh = nh0 + rr;
        int n = nh / H_, h = nh % H_;
        const float* base = x + (((size_t)n * C_ + c4 * 4) * H_ + h) * W_DIM + w4 * 4;
        float4 v0 = *(const float4*)(base);
        float4 v1 = *(const float4*)(base + (size_t)H_ * W_DIM);
        float4 v2 = *(const float4*)(base + (size_t)2 * H_ * W_DIM);
        float4 v3 = *(const float4*)(base + (size_t)3 * H_ * W_DIM);
        float a0[4] = {v0.x, v0.y, v0.z, v0.w};
        float a1[4] = {v1.x, v1.y, v1.z, v1.w};
        float a2[4] = {v2.x, v2.y, v2.z, v2.w};
        float a3[4] = {v3.x, v3.y, v3.z, v3.w};
        #pragma unroll
        for (int i = 0; i < 4; i++) {
            uint32_t word = q8(a0[i], inv) | (q8(a1[i], inv) << 8) |
                            (q8(a2[i], inv) << 16) | (q8(a3[i], inv) << 24);
            sq[rr * (W_DIM * 17) + (4 * w4 + i) * 17 + c4] = word;
        }
    }
    __syncthreads();
    uint32_t* dst = (uint32_t*)g_qx + (size_t)nh0 * (W_DIM * C_ / 4);
    for (int idx = threadIdx.x; idx < 2 * W_DIM * 16; idx += 256) {
        int rr = idx / (W_DIM * 16);
        int rem = idx % (W_DIM * 16);
        int w = rem >> 4, q4 = rem & 15;
        dst[idx] = sq[rr * (W_DIM * 17) + w * 17 + q4];
    }
}

// Quantize W (OIHW) -> g_qw [o][tap*64+c] (K-major rows)
__global__ void quant_w_kernel(const float* __restrict__ Wt) {
    int tid = blockIdx.x * blockDim.x + threadIdx.x;
    if (tid >= NUMEL_W) return;
    int t = tid % 9;
    int oi = tid / 9;
    int c = oi % C_;
    int o = oi / C_;
    float sw = load_scale(1);
    float q = rintf(Wt[tid] / sw);
    q = fminf(fmaxf(q, -127.f), 127.f);
    g_qw[(size_t)o * 576 + t * 64 + c] = (int8_t)(int)q;
}

// ---- persistent hybrid IMMA+dp4a implicit-GEMM conv with cp.async double buffer ----
// Warps 0-7:  o[0:56)   via mma.sync (tensor pipe); nw==1 warps skip their last n-tile.
// Warps 8-15: o[56:128) via register-blocked dp4a (IMAD pipe), 2px x 18o per lane.
// SMEM: B [128 o][576] stride 592 (loaded once), A double-buffer 2 x [128 px][576] stride 592.
#define A_STRIDE 592
#define BUF_BYTES (128 * A_STRIDE)                // 75776
#define SMEM_B   0
#define SMEM_A0  BUF_BYTES
#define SMEM_TOTAL (3 * BUF_BYTES)                // 227328

__device__ __forceinline__ void prefetch_A(uint32_t abuf, int t, int tid) {
    int p0 = t * 128;
    int n_img = p0 / 12544;
    int hw0 = p0 % 12544;
    for (int i = tid; i < 1152; i += 512) {
        int tap = i >> 7, m = i & 127;
        int hw = hw0 + m;
        int h = hw / W_DIM, w = hw % W_DIM;
        int r  = h + tap / 3 - 1;
        int cl = w + tap % 3 - 1;
        bool ok = (r >= 0 && r < H_ && cl >= 0 && cl < W_DIM);
        const char* src = (const char*)(g_qx +
            (((size_t)n_img * H_ + (ok ? r : 0)) * W_DIM + (ok ? cl : 0)) * C_);
        uint32_t dst = abuf + (uint32_t)(m * A_STRIDE + tap * 64);
        int sz = ok ? 16 : 0;
        #pragma unroll
        for (int q = 0; q < 4; q++)
            asm volatile("cp.async.cg.shared.global [%0], [%1], 16, %2;"
                         :: "r"(dst + q * 16), "l"(src + q * 16), "r"(sz));
    }
}

__device__ __forceinline__ int dp4a_(int a, int b, int c) {
    int d;
    asm("dp4a.s32.s32 %0, %1, %2, %3;" : "=r"(d) : "r"(a), "r"(b), "r"(c));
    return d;
}

__global__ void __launch_bounds__(512, 1) gemm_kernel(float* __restrict__ out) {
    extern __shared__ char smem[];
    uint32_t sb = smem_u32(smem);
    int tid = threadIdx.x, wid = tid >> 5, lane = tid & 31;

    // B: loaded ONCE per persistent CTA (128 rows x 576B, stride 592)
    {
        const int4* gB = (const int4*)g_qw;
        for (int i = tid; i < 4608; i += 512) {
            int row = i / 36, col = i % 36;
            *(int4*)(smem + SMEM_B + row * A_STRIDE + col * 16) = gB[row * 36 + col];
        }
    }

    // ---- IMMA warp setup (wid 0-7): 4 m-warps x 2 n-warps; o in [0,56)
    int mw = wid & 3;
    int nw = wid >> 2;           // 0..1 for IMMA warps
    int ntmax = (nw == 0) ? 4 : 3;  // nw1 skips o[56:64)
    int mat = lane >> 3, rin = lane & 7;

    uint32_t aoff[2];
    #pragma unroll
    for (int mt = 0; mt < 2; mt++) {
        int row = mw * 32 + mt * 16 + ((mat & 1) << 3) + rin;
        aoff[mt] = (uint32_t)(row * A_STRIDE + ((mat >> 1) << 4));
    }
    uint32_t bbase[2];
    #pragma unroll
    for (int np = 0; np < 2; np++) {
        int orow = nw * 32 + np * 16 + ((mat >> 1) << 3) + rin;
        bbase[np] = sb + SMEM_B + (uint32_t)(orow * A_STRIDE + ((mat & 1) << 4));
    }

    // ---- dp4a warp setup (wid 8-15): warp covers px [dw*16, +16), lane = 2px x 18o
    int dw = wid - 8;                       // 0..7
    int px0 = dw * 16 + (lane & 7) * 2;     // even
    int ol  = lane >> 3;                    // 0..3
    int og  = O_IMMA + ol * 18;             // o base for this lane (56,74,92,110)

    int t = blockIdx.x;
    int buf = 0;
    if (t < NTILES) prefetch_A(sb + SMEM_A0, t, tid);
    asm volatile("cp.async.commit_group;" ::: "memory");

    for (; t < NTILES; t += GEMM_GRID) {
        int tn = t + GEMM_GRID;
        if (tn < NTILES) prefetch_A(sb + SMEM_A0 + (uint32_t)((buf ^ 1) * BUF_BYTES), tn, tid);
        asm volatile("cp.async.commit_group;" ::: "memory");
        asm volatile("cp.async.wait_group 1;" ::: "memory");
        __syncthreads();

        float* sf = (float*)(smem + SMEM_A0 + (size_t)buf * BUF_BYTES);
        float sc = load_scale(0) * load_scale(1);

        if (wid < 8) {
            // ======== IMMA half: o[0:56) ========
            uint32_t abase = sb + SMEM_A0 + (uint32_t)(buf * BUF_BYTES);
            uint32_t a_addr0 = abase + aoff[0];
            uint32_t a_addr1 = abase + aoff[1];
            uint32_t b_addr0 = bbase[0];
            uint32_t b_addr1 = bbase[1];

            int acc[2][4][4];
            #pragma unroll
            for (int mt = 0; mt < 2; mt++)
                #pragma unroll
                for (int nt = 0; nt < 4; nt++)
                    #pragma unroll
                    for (int k = 0; k < 4; k++) acc[mt][nt][k] = 0;

            #pragma unroll 6
            for (int ks = 0; ks < 18; ks++) {
                uint32_t af[2][4];
                ldsm_x4(af[0][0], af[0][1], af[0][2], af[0][3], a_addr0);
                ldsm_x4(af[1][0], af[1][1], af[1][2], af[1][3], a_addr1);
                a_addr0 += 32; a_addr1 += 32;
                uint32_t bf[4][2];
                ldsm_x4(bf[0][0], bf[0][1], bf[1][0], bf[1][1], b_addr0);
                ldsm_x4(bf[2][0], bf[2][1], bf[3][0], bf[3][1], b_addr1);
                b_addr0 += 32; b_addr1 += 32;
                #pragma unroll
                for (int mt = 0; mt < 2; mt++)
                    #pragma unroll
                    for (int nt = 0; nt < 4; nt++)
                        if (nt < ntmax)
                            mma_s8(acc[mt][nt], af[mt][0], af[mt][1], af[mt][2], af[mt][3],
                                   bf[nt][0], bf[nt][1]);
            }
            __syncthreads();   // all warps done reading A[buf]

            // stage f32 [o][m] stride 132 into A[buf]
            #pragma unroll
            for (int mt = 0; mt < 2; mt++) {
                #pragma unroll
                for (int nt = 0; nt < 4; nt++) {
                    if (nt >= ntmax) continue;
                    int row = mw * 32 + mt * 16 + (lane >> 2);
                    int col = nw * 32 + nt * 8 + (lane & 3) * 2;
                    sf[(col    ) * 132 + row    ] = sc * (float)acc[mt][nt][0];
                    sf[(col + 1) * 132 + row    ] = sc * (float)acc[mt][nt][1];
                    sf[(col    ) * 132 + row + 8] = sc * (float)acc[mt][nt][2];
                    sf[(col + 1) * 132 + row + 8] = sc * (float)acc[mt][nt][3];
                }
            }
        } else {
            // ======== dp4a half: o[56:128), 18 o per lane group ========
            const char* aRow0 = smem + SMEM_A0 + (size_t)buf * BUF_BYTES + px0 * A_STRIDE;
            const char* aRow1 = aRow0 + A_STRIDE;
            const char* bBase = smem + SMEM_B + og * A_STRIDE;

            int acc[2][18];
            #pragma unroll
            for (int p = 0; p < 2; p++)
                #pragma unroll
                for (int j = 0; j < 18; j++) acc[p][j] = 0;

            // k-chunk rotation (kc+ol)%36 derotates B bank conflicts across lane groups;
            // integer accumulation is order-independent -> bitwise identical results.
            uint32_t off = (uint32_t)ol * 16;
            #pragma unroll 2
            for (int kc = 0; kc < 36; kc++) {
                int4 a0 = *(const int4*)(aRow0 + off);
                int4 a1 = *(const int4*)(aRow1 + off);
                const char* bp = bBase + off;
                #pragma unroll
                for (int j = 0; j < 18; j++) {
                    int4 b = *(const int4*)(bp + j * A_STRIDE);
                    acc[0][j] = dp4a_(a0.x, b.x, acc[0][j]);
                    acc[0][j] = dp4a_(a0.y, b.y, acc[0][j]);
                    acc[0][j] = dp4a_(a0.z, b.z, acc[0][j]);
                    acc[0][j] = dp4a_(a0.w, b.w, acc[0][j]);
                    acc[1][j] = dp4a_(a1.x, b.x, acc[1][j]);
                    acc[1][j] = dp4a_(a1.y, b.y, acc[1][j]);
                    acc[1][j] = dp4a_(a1.z, b.z, acc[1][j]);
                    acc[1][j] = dp4a_(a1.w, b.w, acc[1][j]);
                }
                off += 16;
                if (off == 576) off = 0;
            }
            __syncthreads();   // all warps done reading A[buf]

            // stage f32: float2 per (o, px-pair)
            #pragma unroll
            for (int j = 0; j < 18; j++) {
                int col = og + j;
                float2 v = make_float2(sc * (float)acc[0][j], sc * (float)acc[1][j]);
                *(float2*)&sf[col * 132 + px0] = v;
            }
        }
        __syncthreads();

        int p0 = t * 128;
        int n_img = p0 / 12544;
        int hw0   = p0 % 12544;
        float* obase = out + (size_t)n_img * O_ * 12544 + hw0;
        for (int i = tid; i < 128 * 32; i += 512) {
            int o = i >> 5, seg = i & 31;
            float4 v = *(float4*)&sf[o * 132 + seg * 4];
            *(float4*)(obase + (size_t)o * 12544 + seg * 4) = v;
        }
        __syncthreads();   // sf reads done before this buffer is prefetched again
        buf ^= 1;
    }
}

// ---- checker: recompute 4096 samples via dp4a, bitwise compare ----
__global__ void check_kernel(const float* __restrict__ out) {
    int s = blockIdx.x * blockDim.x + threadIdx.x;          // 0..4095
    int p = (int)(((long long)s * 49157) % NPIX);
    int o = (s * 37) & 127;
    int n = p / 12544, hw = p % 12544;
    int h = hw / W_DIM, w = hw % W_DIM;
    int acc = 0;
    #pragma unroll
    for (int t = 0; t < 9; t++) {
        int r = h + t / 3 - 1, cl = w + t % 3 - 1;
        if (r < 0 || r >= H_ || cl < 0 || cl >= W_DIM) continue;
        const int* xp = (const int*)(g_qx + (((size_t)n * H_ + r) * W_DIM + cl) * C_);
        const int* wp = (const int*)(g_qw + (size_t)o * 576 + t * 64);
        #pragma unroll
        for (int q = 0; q < 16; q++) acc = __dp4a(xp[q], wp[q], acc);
    }
    float ref = load_scale(0) * load_scale(1) * (float)acc;
    if (out[((size_t)n * O_ + o) * 12544 + h * W_DIM + w] != ref)
        g_flag = 1;
}

// ---- fallback: proven dp4a direct conv (gated on g_flag) ----
__global__ void __launch_bounds__(256) conv_kernel(float* __restrict__ out) {
    if (g_flag == 0) return;
    __shared__ int s_in[16 * 3 * 34];
    __shared__ int s_w[64 * 9 * 16];

    int w0 = blockIdx.x * TILE_W;
    int h  = blockIdx.y;
    int half = blockIdx.z & 1;
    int n    = blockIdx.z >> 1;
    int tid = threadIdx.x;

    for (int i = tid; i < 9216; i += 256) {
        int q = i & 15, to = i >> 4;
        int t = to % 9, o = to / 9;
        s_w[i] = *(const int*)(g_qw + (size_t)(half * 64 + o) * 576 + t * 64 + q * 4);
    }

    const uint32_t* gx = (const uint32_t*)g_qx;
    for (int idx = tid; idx < 1632; idx += 256) {
        int q  = idx & 15;
        int rc = idx >> 4;
        int col = rc % 34, r = rc / 34;
        int row = h + r - 1;
        int w   = w0 + col - 1;
        uint32_t v = 0;
        if (row >= 0 && row < H_ && w >= 0 && w < W_DIM)
            v = gx[(((size_t)n * H_ + row) * W_DIM + w) * 16 + q];
        s_in[(q * 3 + r) * 34 + col] = (int)v;
    }
    __syncthreads();

    int px = tid & 31;
    int cg = tid >> 5;

    int acc[8];
    #pragma unroll
    for (int k = 0; k < 8; k++) acc[k] = 0;

    #pragma unroll
    for (int t = 0; t < 9; t++) {
        const int r = t / 3, dx = t % 3;
        int inw[16];
        #pragma unroll
        for (int q = 0; q < 16; q++)
            inw[q] = s_in[(q * 3 + r) * 34 + px + dx];
        #pragma unroll
        for (int k = 0; k < 8; k++) {
            const int4* wp = (const int4*)&s_w[((cg * 8 + k) * 9 + t) * 16];
            #pragma unroll
            for (int q4 = 0; q4 < 4; q4++) {
                int4 wv = wp[q4];
                acc[k] = __dp4a(inw[q4 * 4 + 0], wv.x, acc[k]);
                acc[k] = __dp4a(inw[q4 * 4 + 1], wv.y, acc[k]);
                acc[k] = __dp4a(inw[q4 * 4 + 2], wv.z, acc[k]);
                acc[k] = __dp4a(inw[q4 * 4 + 3], wv.w, acc[k]);
            }
        }
    }

    int w = w0 + px;
    if (w < W_DIM) {
        float sc = load_scale(0) * load_scale(1);
        #pragma unroll
        for (int k = 0; k < 8; k++) {
            int o = half * 64 + cg * 8 + k;
            out[(((size_t)n * O_ + o) * H_ + h) * W_DIM + w] = sc * (float)acc[k];
        }
    }
}

extern "C" void kernel_launch(void* const* d_in, const int* in_sizes, int n_in,
                              void* d_out, int out_size) {
    const float* x  = (const float*)d_in[0];
    const float* Wt = (const float*)d_in[1];
    float* out = (float*)d_out;

    cudaFuncSetAttribute(gemm_kernel, cudaFuncAttributeMaxDynamicSharedMemorySize, SMEM_TOTAL);

    init_kernel<<<1, 1>>>();
    absmax_kernel<<<2048, 256>>>((const float4*)x,  NUMEL_X / 4, 0);
    absmax_kernel<<<72,   256>>>((const float4*)Wt, NUMEL_W / 4, 1);
    quant_x_kernel<<<N_ * H_ / 2, 256>>>(x);
    quant_w_kernel<<<(NUMEL_W + 255) / 256, 256>>>(Wt);

    gemm_kernel<<<GEMM_GRID, 512, SMEM_TOTAL>>>(out);

    check_kernel<<<16, 256>>>(out);

    dim3 grid((W_DIM + TILE_W - 1) / TILE_W, H_, N_ * 2);
    conv_kernel<<<grid, 256>>>(out);
}

// round 16
// speedup vs baseline: 1.2295x; 1.2295x over previous
#include <cuda_runtime.h>
#include <cstdint>
#include <cstddef>

#define N_    16
#define C_    64
#define H_    112
#define W_DIM 112
#define O_    128
#define NUMEL_X (N_*C_*H_*W_DIM)   // 12,845,056
#define NUMEL_W (O_*C_*9)          // 73,728
#define NPIX   (N_*H_*W_DIM)       // 200704 pixels
#define NTILES (NPIX/128)          // 1568  (12544 = 98*128: tiles never cross n)
#define GEMM_GRID 148

// ---- device scratch (no allocation allowed) ----
__device__ unsigned int g_absmax[2];               // [0]=x, [1]=W (float bits, >=0)
__device__ int8_t g_qx[(size_t)NPIX*C_];           // NHWC int8
__device__ int8_t g_qw[(size_t)O_*9*C_];           // [O][tap*64+c] int8 (= B rows, K-major)

__device__ __forceinline__ uint32_t smem_u32(const void* p) {
    uint32_t a;
    asm("{ .reg .u64 t; cvta.to.shared.u64 t, %1; cvt.u32.u64 %0, t; }" : "=r"(a) : "l"(p));
    return a;
}

// ---- warp-level int8 tensor core ops (base-target PTX, no tcgen05) ----
__device__ __forceinline__ void ldsm_x4(uint32_t& r0, uint32_t& r1, uint32_t& r2, uint32_t& r3,
                                        uint32_t addr) {
    asm volatile("ldmatrix.sync.aligned.m8n8.x4.shared.b16 {%0,%1,%2,%3}, [%4];"
                 : "=r"(r0), "=r"(r1), "=r"(r2), "=r"(r3) : "r"(addr));
}

__device__ __forceinline__ void mma_s8(int* c, uint32_t a0, uint32_t a1, uint32_t a2, uint32_t a3,
                                       uint32_t b0, uint32_t b1) {
    asm volatile("mma.sync.aligned.m16n8k32.row.col.s32.s8.s8.s32 "
                 "{%0,%1,%2,%3}, {%4,%5,%6,%7}, {%8,%9}, {%0,%1,%2,%3};"
                 : "+r"(c[0]), "+r"(c[1]), "+r"(c[2]), "+r"(c[3])
                 : "r"(a0), "r"(a1), "r"(a2), "r"(a3), "r"(b0), "r"(b1));
}

// ---- common small kernels ----
__global__ void init_kernel() {
    g_absmax[0] = 0u;
    g_absmax[1] = 0u;
}

__device__ __forceinline__ void block_max_atomic(float v, unsigned int* target) {
    #pragma unroll
    for (int off = 16; off; off >>= 1)
        v = fmaxf(v, __shfl_xor_sync(0xffffffffu, v, off));
    __shared__ float s[32];
    int lane = threadIdx.x & 31, wid = threadIdx.x >> 5;
    if (lane == 0) s[wid] = v;
    __syncthreads();
    if (wid == 0) {
        int nw = (blockDim.x + 31) >> 5;
        v = (lane < nw) ? s[lane] : 0.f;
        #pragma unroll
        for (int off = 16; off; off >>= 1)
            v = fmaxf(v, __shfl_xor_sync(0xffffffffu, v, off));
        if (lane == 0) atomicMax(target, __float_as_uint(v));
    }
}

__global__ void absmax_kernel(const float4* __restrict__ p, int n4, int which) {
    float m = 0.f;
    for (int i = blockIdx.x * blockDim.x + threadIdx.x; i < n4; i += gridDim.x * blockDim.x) {
        float4 v = p[i];
        m = fmaxf(m, fmaxf(fmaxf(fabsf(v.x), fabsf(v.y)), fmaxf(fabsf(v.z), fabsf(v.w))));
    }
    block_max_atomic(m, &g_absmax[which]);
}

__device__ __forceinline__ float load_scale(int which) {
    return fmaxf(__uint_as_float(g_absmax[which]) / 127.0f, 1e-8f);
}

__device__ __forceinline__ uint32_t q8(float v, float inv) {
    float q = fminf(fmaxf(rintf(v * inv), -127.f), 127.f);
    return (uint32_t)(uint8_t)(int8_t)(int)q;
}

// Quantize x NCHW -> NHWC int8. One block per (n,h).
__global__ void __launch_bounds__(256) quant_x_kernel(const float* __restrict__ x) {
    __shared__ uint32_t sq[W_DIM * 17];
    int nh = blockIdx.x;
    int n = nh / H_, h = nh % H_;
    float inv = 1.0f / load_scale(0);
    for (int idx = threadIdx.x; idx < 448; idx += 256) {
        int c4 = idx / 28, w4 = idx % 28;
        const float* base = x + (((size_t)n * C_ + c4 * 4) * H_ + h) * W_DIM + w4 * 4;
        float4 v0 = *(const float4*)(base);
        float4 v1 = *(const float4*)(base + (size_t)H_ * W_DIM);
        float4 v2 = *(const float4*)(base + (size_t)2 * H_ * W_DIM);
        float4 v3 = *(const float4*)(base + (size_t)3 * H_ * W_DIM);
        float a0[4] = {v0.x, v0.y, v0.z, v0.w};
        float a1[4] = {v1.x, v1.y, v1.z, v1.w};
        float a2[4] = {v2.x, v2.y, v2.z, v2.w};
        float a3[4] = {v3.x, v3.y, v3.z, v3.w};
        #pragma unroll
        for (int i = 0; i < 4; i++) {
            uint32_t word = q8(a0[i], inv) | (q8(a1[i], inv) << 8) |
                            (q8(a2[i], inv) << 16) | (q8(a3[i], inv) << 24);
            sq[(4 * w4 + i) * 17 + c4] = word;
        }
    }
    __syncthreads();
    uint32_t* dst = (uint32_t*)g_qx + (size_t)nh * (W_DIM * C_ / 4);
    for (int idx = threadIdx.x; idx < W_DIM * 16; idx += 256) {
        int w = idx >> 4, q4 = idx & 15;
        dst[idx] = sq[w * 17 + q4];
    }
}

// Quantize W (OIHW) -> g_qw [o][tap*64+c] (K-major rows)
__global__ void quant_w_kernel(const float* __restrict__ Wt) {
    int tid = blockIdx.x * blockDim.x + threadIdx.x;
    if (tid >= NUMEL_W) return;
    int t = tid % 9;
    int oi = tid / 9;
    int c = oi % C_;
    int o = oi / C_;
    float sw = load_scale(1);
    float q = rintf(Wt[tid] / sw);
    q = fminf(fmaxf(q, -127.f), 127.f);
    g_qw[(size_t)o * 576 + t * 64 + c] = (int8_t)(int)q;
}

// ---- persistent hybrid IMMA+dp4a implicit-GEMM conv with cp.async double buffer ----
// Warps 0-7:  o[0:64)  via mma.sync (tensor pipe), proven fragment mapping.
// Warps 8-15: o[64:128) via register-blocked dp4a (IMAD pipe), 2px x 16o per lane.
// SMEM: B [128 o][576] stride 592 (loaded once), A double-buffer 2 x [128 px][576] stride 592.
#define A_STRIDE 592
#define BUF_BYTES (128 * A_STRIDE)                // 75776
#define SMEM_B   0
#define SMEM_A0  BUF_BYTES
#define SMEM_TOTAL (3 * BUF_BYTES)                // 227328

__device__ __forceinline__ void prefetch_A(uint32_t abuf, int t, int tid) {
    int p0 = t * 128;
    int n_img = p0 / 12544;
    int hw0 = p0 % 12544;
    for (int i = tid; i < 1152; i += 512) {
        int tap = i >> 7, m = i & 127;
        int hw = hw0 + m;
        int h = hw / W_DIM, w = hw % W_DIM;
        int r  = h + tap / 3 - 1;
        int cl = w + tap % 3 - 1;
        bool ok = (r >= 0 && r < H_ && cl >= 0 && cl < W_DIM);
        const char* src = (const char*)(g_qx +
            (((size_t)n_img * H_ + (ok ? r : 0)) * W_DIM + (ok ? cl : 0)) * C_);
        uint32_t dst = abuf + (uint32_t)(m * A_STRIDE + tap * 64);
        int sz = ok ? 16 : 0;
        #pragma unroll
        for (int q = 0; q < 4; q++)
            asm volatile("cp.async.cg.shared.global [%0], [%1], 16, %2;"
                         :: "r"(dst + q * 16), "l"(src + q * 16), "r"(sz));
    }
}

__device__ __forceinline__ int dp4a_(int a, int b, int c) {
    int d;
    asm("dp4a.s32.s32 %0, %1, %2, %3;" : "=r"(d) : "r"(a), "r"(b), "r"(c));
    return d;
}

__global__ void __launch_bounds__(512, 1) gemm_kernel(float* __restrict__ out) {
    extern __shared__ char smem[];
    uint32_t sb = smem_u32(smem);
    int tid = threadIdx.x, wid = tid >> 5, lane = tid & 31;

    // B: loaded ONCE per persistent CTA (128 rows x 576B, stride 592)
    {
        const int4* gB = (const int4*)g_qw;
        for (int i = tid; i < 4608; i += 512) {
            int row = i / 36, col = i % 36;
            *(int4*)(smem + SMEM_B + row * A_STRIDE + col * 16) = gB[row * 36 + col];
        }
    }

    // ---- IMMA warp setup (wid 0-7): 4 m-warps x 2 n-warps; warp = 32px x 32o, o in [0,64)
    int mw = wid & 3;
    int nw = wid >> 2;           // 0..1 for IMMA warps
    int mat = lane >> 3, rin = lane & 7;

    uint32_t aoff[2];
    #pragma unroll
    for (int mt = 0; mt < 2; mt++) {
        int row = mw * 32 + mt * 16 + ((mat & 1) << 3) + rin;
        aoff[mt] = (uint32_t)(row * A_STRIDE + ((mat >> 1) << 4));
    }
    uint32_t bbase[2];
    #pragma unroll
    for (int np = 0; np < 2; np++) {
        int orow = nw * 32 + np * 16 + ((mat >> 1) << 3) + rin;
        bbase[np] = sb + SMEM_B + (uint32_t)(orow * A_STRIDE + ((mat & 1) << 4));
    }

    // ---- dp4a warp setup (wid 8-15): warp covers px [dw*16, dw*16+16), lane = 2px x 16o
    int dw = wid - 8;                       // 0..7
    int px0 = dw * 16 + (lane & 7) * 2;     // even
    int ol  = lane >> 3;                    // 0..3
    int og  = 64 + ol * 16;                 // o base for this lane

    int t = blockIdx.x;
    int buf = 0;
    if (t < NTILES) prefetch_A(sb + SMEM_A0, t, tid);
    asm volatile("cp.async.commit_group;" ::: "memory");

    for (; t < NTILES; t += GEMM_GRID) {
        int tn = t + GEMM_GRID;
        if (tn < NTILES) prefetch_A(sb + SMEM_A0 + (uint32_t)((buf ^ 1) * BUF_BYTES), tn, tid);
        asm volatile("cp.async.commit_group;" ::: "memory");
        asm volatile("cp.async.wait_group 1;" ::: "memory");
        __syncthreads();

        float* sf = (float*)(smem + SMEM_A0 + (size_t)buf * BUF_BYTES);
        float sc = load_scale(0) * load_scale(1);

        if (wid < 8) {
            // ======== IMMA half: o[0:64) ========
            uint32_t abase = sb + SMEM_A0 + (uint32_t)(buf * BUF_BYTES);
            uint32_t a_addr0 = abase + aoff[0];
            uint32_t a_addr1 = abase + aoff[1];
            uint32_t b_addr0 = bbase[0];
            uint32_t b_addr1 = bbase[1];

            int acc[2][4][4];
            #pragma unroll
            for (int mt = 0; mt < 2; mt++)
                #pragma unroll
                for (int nt = 0; nt < 4; nt++)
                    #pragma unroll
                    for (int k = 0; k < 4; k++) acc[mt][nt][k] = 0;

            #pragma unroll 6
            for (int ks = 0; ks < 18; ks++) {
                uint32_t af[2][4];
                ldsm_x4(af[0][0], af[0][1], af[0][2], af[0][3], a_addr0);
                ldsm_x4(af[1][0], af[1][1], af[1][2], af[1][3], a_addr1);
                a_addr0 += 32; a_addr1 += 32;
                uint32_t bf[4][2];
                ldsm_x4(bf[0][0], bf[0][1], bf[1][0], bf[1][1], b_addr0);
                ldsm_x4(bf[2][0], bf[2][1], bf[3][0], bf[3][1], b_addr1);
                b_addr0 += 32; b_addr1 += 32;
                #pragma unroll
                for (int mt = 0; mt < 2; mt++)
                    #pragma unroll
                    for (int nt = 0; nt < 4; nt++)
                        mma_s8(acc[mt][nt], af[mt][0], af[mt][1], af[mt][2], af[mt][3],
                               bf[nt][0], bf[nt][1]);
            }
            __syncthreads();   // all warps done reading A[buf]

            // stage f32 [o][m] stride 132 into A[buf]
            #pragma unroll
            for (int mt = 0; mt < 2; mt++) {
                #pragma unroll
                for (int nt = 0; nt < 4; nt++) {
                    int row = mw * 32 + mt * 16 + (lane >> 2);
                    int col = nw * 32 + nt * 8 + (lane & 3) * 2;
                    sf[(col    ) * 132 + row    ] = sc * (float)acc[mt][nt][0];
                    sf[(col + 1) * 132 + row    ] = sc * (float)acc[mt][nt][1];
                    sf[(col    ) * 132 + row + 8] = sc * (float)acc[mt][nt][2];
                    sf[(col + 1) * 132 + row + 8] = sc * (float)acc[mt][nt][3];
                }
            }
        } else {
            // ======== dp4a half: o[64:128) ========
            const char* aRow0 = smem + SMEM_A0 + (size_t)buf * BUF_BYTES + px0 * A_STRIDE;
            const char* aRow1 = aRow0 + A_STRIDE;
            const char* bBase = smem + SMEM_B + og * A_STRIDE;

            int acc[2][16];
            #pragma unroll
            for (int p = 0; p < 2; p++)
                #pragma unroll
                for (int j = 0; j < 16; j++) acc[p][j] = 0;

            // k-chunk rotation (kc+ol)%36 derotates B bank conflicts across lane groups;
            // integer accumulation is order-independent -> bitwise identical results.
            uint32_t off = (uint32_t)ol * 16;
            #pragma unroll 2
            for (int kc = 0; kc < 36; kc++) {
                int4 a0 = *(const int4*)(aRow0 + off);
                int4 a1 = *(const int4*)(aRow1 + off);
                const char* bp = bBase + off;
                #pragma unroll
                for (int j = 0; j < 16; j++) {
                    int4 b = *(const int4*)(bp + j * A_STRIDE);
                    acc[0][j] = dp4a_(a0.x, b.x, acc[0][j]);
                    acc[0][j] = dp4a_(a0.y, b.y, acc[0][j]);
                    acc[0][j] = dp4a_(a0.z, b.z, acc[0][j]);
                    acc[0][j] = dp4a_(a0.w, b.w, acc[0][j]);
                    acc[1][j] = dp4a_(a1.x, b.x, acc[1][j]);
                    acc[1][j] = dp4a_(a1.y, b.y, acc[1][j]);
                    acc[1][j] = dp4a_(a1.z, b.z, acc[1][j]);
                    acc[1][j] = dp4a_(a1.w, b.w, acc[1][j]);
                }
                off += 16;
                if (off == 576) off = 0;
            }
            __syncthreads();   // all warps done reading A[buf]

            // stage f32: float2 per (o, px-pair)
            #pragma unroll
            for (int j = 0; j < 16; j++) {
                int col = og + j;
                float2 v = make_float2(sc * (float)acc[0][j], sc * (float)acc[1][j]);
                *(float2*)&sf[col * 132 + px0] = v;
            }
        }
        __syncthreads();

        int p0 = t * 128;
        int n_img = p0 / 12544;
        int hw0   = p0 % 12544;
        float* obase = out + (size_t)n_img * O_ * 12544 + hw0;
        for (int i = tid; i < 128 * 32; i += 512) {
            int o = i >> 5, seg = i & 31;
            float4 v = *(float4*)&sf[o * 132 + seg * 4];
            *(float4*)(obase + (size_t)o * 12544 + seg * 4) = v;
        }
        __syncthreads();   // sf reads done before this buffer is prefetched again
        buf ^= 1;
    }
}

extern "C" void kernel_launch(void* const* d_in, const int* in_sizes, int n_in,
                              void* d_out, int out_size) {
    const float* x  = (const float*)d_in[0];
    const float* Wt = (const float*)d_in[1];
    float* out = (float*)d_out;

    cudaFuncSetAttribute(gemm_kernel, cudaFuncAttributeMaxDynamicSharedMemorySize, SMEM_TOTAL);

    init_kernel<<<1, 1>>>();
    absmax_kernel<<<2048, 256>>>((const float4*)x,  NUMEL_X / 4, 0);
    absmax_kernel<<<72,   256>>>((const float4*)Wt, NUMEL_W / 4, 1);
    quant_x_kernel<<<N_ * H_, 256>>>(x);
    quant_w_kernel<<<(NUMEL_W + 255) / 256, 256>>>(Wt);

    gemm_kernel<<<GEMM_GRID, 512, SMEM_TOTAL>>>(out);
}